// round 14
// baseline (speedup 1.0000x reference)
#include <cuda_runtime.h>
#include <math.h>
#include <stdint.h>

// Problem dims
#define CH   768
#define H_   180
#define W_   360
#define WK   91           // kept W modes (rfft bins 0..90; 91..180 provably zero)
#define NB   8
#define BS   96
#define S_   (H_ * WK)    // 16380 spectral points per channel
#define ROWS (CH * H_)    // 138240 spatial rows
#define ORTHO 0.003928371006591931f   // 1/sqrt(180*360)
#define LAM  0.01f

// Scratch buffers
__device__ float2 g_S1[(size_t)CH * S_];
__device__ float2 g_S2[(size_t)CH * S_];

// Precomputed tf32 DFT tables + fp32 H twiddles
__device__ uint32_t g_TC[192 * 96];   // fwd: [n][w] = tf32(cos(t n w)); 0 outside
__device__ uint32_t g_TS[192 * 96];   // fwd: [n][w] = tf32(-sin(t n w))
__device__ uint32_t g_UC[96 * 192];   // inv: [w][n] = tf32(cos); w=0 -> 0.5
__device__ uint32_t g_VS[96 * 192];   // inv: [w][n] = tf32(sin); w=0 -> 0
__device__ float2 g_twHf[H_];         // e^{-2pi i n/180}
__device__ float2 g_twHb[H_];         // e^{+2pi i n/180}

__device__ __forceinline__ float2 cmul(float2 a, float2 b) {
    return make_float2(fmaf(a.x, b.x, -a.y * b.y),
                       fmaf(a.x, b.y,  a.y * b.x));
}

__device__ __forceinline__ uint32_t f2tf(float f) {
    uint32_t u;
    asm("cvt.rna.tf32.f32 %0, %1;" : "=r"(u) : "f"(f));
    return u;
}

__device__ __forceinline__ void mma_tf32(float* d,
    uint32_t a0, uint32_t a1, uint32_t a2, uint32_t a3,
    uint32_t b0, uint32_t b1) {
    asm volatile(
        "mma.sync.aligned.m16n8k8.row.col.f32.tf32.tf32.f32 "
        "{%0,%1,%2,%3}, {%4,%5,%6,%7}, {%8,%9}, {%0,%1,%2,%3};"
        : "+f"(d[0]), "+f"(d[1]), "+f"(d[2]), "+f"(d[3])
        : "r"(a0), "r"(a1), "r"(a2), "r"(a3), "r"(b0), "r"(b1));
}

// ---------------------------------------------------------------------------
// Init: tf32 DFT tables + H twiddles.
// ---------------------------------------------------------------------------
__global__ void k_init_T() {
    int i = blockIdx.x * 256 + threadIdx.x;
    if (i < 192 * 96) {                      // fwd tables [n][w]
        int n = i / 96, w = i % 96;
        float cv = 0.f, sv = 0.f;
        if (n <= 180 && w <= 90) {
            float s, c;
            sincospif((float)((n * w) % 360) / 180.0f, &s, &c);
            cv = c; sv = -s;
        }
        g_TC[i] = f2tf(cv);
        g_TS[i] = f2tf(sv);
    }
    if (i < 96 * 192) {                      // inv tables [w][n]
        int w = i / 192, n = i % 192;
        float uc = 0.f, vs = 0.f;
        if (n <= 180 && w <= 90) {
            if (w == 0) { uc = 0.5f; vs = 0.f; }
            else {
                float s, c;
                sincospif((float)((n * w) % 360) / 180.0f, &s, &c);
                uc = c; vs = s;
            }
        }
        g_UC[i] = f2tf(uc);
        g_VS[i] = f2tf(vs);
    }
    if (i < H_) {
        float s, c;
        sincospif((float)i / 90.0f, &s, &c);
        g_twHf[i] = make_float2(c, -s);
        g_twHb[i] = make_float2(c,  s);
    }
}

// ---------------------------------------------------------------------------
// Kernel 1: forward W r2c DFT on TENSOR CORES (tf32).
// re[row][w] = sum_n p[n]*cos, im[row][w] = sum_n m[n]*(-sin); single fold
// p[n]=x[n]+x[360-n], m[n]=x[n]-x[360-n] (n=0/180 impurities killed by sin=0).
// M=96 bins (6 warps x 16), K=192 (chunks of 32), N=64 rows/tile.
// ---------------------------------------------------------------------------
#define FPT 104
#define FPD 72
__global__ __launch_bounds__(192)
void k_fwd_w(const float* __restrict__ x) {
    __shared__ uint32_t TC[32 * FPT], TS[32 * FPT];
    __shared__ uint32_t Pp[32 * FPD], Mm[32 * FPD];
    int r0  = blockIdx.x * 64;
    int tid = threadIdx.x;
    int wrp = tid >> 5, lane = tid & 31;
    int q = lane >> 2, r = lane & 3;
    int wb = wrp * 16;

    float Or[8][4], Oi[8][4];
    #pragma unroll
    for (int t = 0; t < 8; t++)
        #pragma unroll
        for (int c = 0; c < 4; c++) { Or[t][c] = 0.f; Oi[t][c] = 0.f; }

    for (int nc = 0; nc < 192; nc += 32) {
        for (int t = tid; t < 32 * 96; t += 192) {
            int i = t / 96, w = t % 96;
            TC[i * FPT + w] = g_TC[(nc + i) * 96 + w];
            TS[i * FPT + w] = g_TS[(nc + i) * 96 + w];
        }
        for (int t = tid; t < 32 * 64; t += 192) {
            int i = t & 31, j = t >> 5;
            int n = nc + i;
            const float* xr = x + (size_t)(r0 + j) * W_;
            float a = (n <= 180) ? xr[n] : 0.f;
            float b = (n >= 1 && n <= 179) ? xr[W_ - n] : 0.f;
            Pp[i * FPD + j] = f2tf(a + b);
            Mm[i * FPD + j] = f2tf(a - b);
        }
        __syncthreads();
        #pragma unroll
        for (int k0 = 0; k0 < 32; k0 += 8) {
            uint32_t ac0 = TC[(k0 + r) * FPT + wb + q];
            uint32_t ac1 = TC[(k0 + r) * FPT + wb + q + 8];
            uint32_t ac2 = TC[(k0 + r + 4) * FPT + wb + q];
            uint32_t ac3 = TC[(k0 + r + 4) * FPT + wb + q + 8];
            uint32_t as0 = TS[(k0 + r) * FPT + wb + q];
            uint32_t as1 = TS[(k0 + r) * FPT + wb + q + 8];
            uint32_t as2 = TS[(k0 + r + 4) * FPT + wb + q];
            uint32_t as3 = TS[(k0 + r + 4) * FPT + wb + q + 8];
            #pragma unroll
            for (int t = 0; t < 8; t++) {
                uint32_t bp0 = Pp[(k0 + r) * FPD + 8 * t + q];
                uint32_t bp1 = Pp[(k0 + r + 4) * FPD + 8 * t + q];
                uint32_t bm0 = Mm[(k0 + r) * FPD + 8 * t + q];
                uint32_t bm1 = Mm[(k0 + r + 4) * FPD + 8 * t + q];
                mma_tf32(Or[t], ac0, ac1, ac2, ac3, bp0, bp1);
                mma_tf32(Oi[t], as0, as1, as2, as3, bm0, bm1);
            }
        }
        __syncthreads();
    }
    #pragma unroll
    for (int t = 0; t < 8; t++) {
        #pragma unroll
        for (int c = 0; c < 4; c++) {
            int bin = wb + q + ((c >= 2) ? 8 : 0);
            int row = r0 + 8 * t + 2 * r + (c & 1);
            if (bin < WK)
                g_S1[(size_t)row * WK + bin] =
                    make_float2(Or[t][c] * ORTHO, Oi[t][c] * ORTHO);
        }
    }
}

// ---------------------------------------------------------------------------
// Kernels 2/5: 180-pt complex DFT along H, radix-4 sharing + 3-way k-blocking.
// (unchanged from R13 passing version)
// ---------------------------------------------------------------------------
#define WT 13
template <int SGN>
__global__ __launch_bounds__(224)
void k_fft_h(const float2* __restrict__ in, float2* __restrict__ out) {
    __shared__ float2 tile[H_ * WT];
    __shared__ float2 tw[H_];
    int c  = blockIdx.y;
    int w0 = blockIdx.x * WT;
    const float2* base = in + (size_t)c * S_;
    for (int i = threadIdx.x; i < H_ * WT; i += 224) {
        int h = i / WT, wl = i % WT;
        tile[i] = base[(size_t)h * WK + w0 + wl];
    }
    const float2* gt = (SGN < 0) ? g_twHf : g_twHb;
    for (int n = threadIdx.x; n < H_; n += 224) tw[n] = gt[n];
    __syncthreads();

    int tid = threadIdx.x;
    if (tid < 195) {
        int k0 = tid / WT, wl = tid % WT;    // k0 in [0,15)
        float2 w60  = tw[60];
        float2 w120 = tw[120];
        int s4 = 4 * k0;

        float2 A[3][4];
        #pragma unroll
        for (int t = 0; t < 3; t++)
            #pragma unroll
            for (int j = 0; j < 4; j++) A[t][j] = make_float2(0.f, 0.f);

        int idx = 0;
        #pragma unroll 3
        for (int q = 0; q < 15; q++) {
            #pragma unroll
            for (int u = 0; u < 3; u++) {
                int r = 3 * q + u;
                float2 e0 = tw[idx];
                float2 e1, e2;
                if (u == 0)      { e1 = e0; e2 = e0; }
                else if (u == 1) { e1 = cmul(e0, w60);  e2 = cmul(e0, w120); }
                else             { e1 = cmul(e0, w120); e2 = cmul(e0, w60);  }
                float2 z0 = tile[(4 * r + 0) * WT + wl];
                float2 z1 = tile[(4 * r + 1) * WT + wl];
                float2 z2 = tile[(4 * r + 2) * WT + wl];
                float2 z3 = tile[(4 * r + 3) * WT + wl];
                #pragma unroll
                for (int t = 0; t < 3; t++) {
                    float2 e = (t == 0) ? e0 : (t == 1) ? e1 : e2;
                    A[t][0].x = fmaf(z0.x, e.x, fmaf(-z0.y, e.y, A[t][0].x));
                    A[t][0].y = fmaf(z0.x, e.y, fmaf( z0.y, e.x, A[t][0].y));
                    A[t][1].x = fmaf(z1.x, e.x, fmaf(-z1.y, e.y, A[t][1].x));
                    A[t][1].y = fmaf(z1.x, e.y, fmaf( z1.y, e.x, A[t][1].y));
                    A[t][2].x = fmaf(z2.x, e.x, fmaf(-z2.y, e.y, A[t][2].x));
                    A[t][2].y = fmaf(z2.x, e.y, fmaf( z2.y, e.x, A[t][2].y));
                    A[t][3].x = fmaf(z3.x, e.x, fmaf(-z3.y, e.y, A[t][3].x));
                    A[t][3].y = fmaf(z3.x, e.y, fmaf( z3.y, e.x, A[t][3].y));
                }
                idx += s4; if (idx >= H_) idx -= H_;
            }
        }

        float2* ob = out + (size_t)c * S_;
        #pragma unroll
        for (int t = 0; t < 3; t++) {
            int kt = k0 + 15 * t;
            float2 PP = A[t][0], QP = A[t][1], PQ = A[t][2], QQ = A[t][3];
            float2 w1t = tw[kt];
            float2 w2t = tw[2 * kt];
            float2 t2  = cmul(w2t, PQ);
            float2 t2q = cmul(w2t, QQ);
            float2 Pp = make_float2(PP.x + t2.x,  PP.y + t2.y);
            float2 Pm = make_float2(PP.x - t2.x,  PP.y - t2.y);
            float2 Qp = make_float2(QP.x + t2q.x, QP.y + t2q.y);
            float2 Qm = make_float2(QP.x - t2q.x, QP.y - t2q.y);
            float2 up = cmul(w1t, Qp);
            float2 um = cmul(w1t, Qm);
            float2 iu = make_float2((float)(-SGN) * um.y, (float)SGN * um.x);
            size_t o0 = (size_t)kt * WK + w0 + wl;
            ob[o0           ] = make_float2(Pp.x + up.x, Pp.y + up.y);
            ob[o0 +  45 * WK] = make_float2(Pm.x + iu.x, Pm.y + iu.y);
            ob[o0 +  90 * WK] = make_float2(Pp.x - up.x, Pp.y - up.y);
            ob[o0 + 135 * WK] = make_float2(Pm.x - iu.x, Pm.y - iu.y);
        }
    }
}

// ---------------------------------------------------------------------------
// Kernels 3+4 fused on TENSOR CORES (tf32 mma.m16n8k8).
// (unchanged from R13 passing version)
// ---------------------------------------------------------------------------
#define PW 104
#define PA 72
#define MIX_SMEM_WORDS (2*32*PW + 2*32*PA + 2*96*PA)

__global__ __launch_bounds__(192)
void k_mix_f(const float2* __restrict__ in, float2* __restrict__ out,
             const float* __restrict__ w1_, const float* __restrict__ b1_,
             const float* __restrict__ w2_, const float* __restrict__ b2_) {
    extern __shared__ uint32_t smu[];
    uint32_t* WSR = smu;                       // 32*PW
    uint32_t* WSI = WSR + 32 * PW;
    uint32_t* ASR = WSI + 32 * PW;             // 32*PA
    uint32_t* ASI = ASR + 32 * PA;
    uint32_t* O1R = ASI + 32 * PA;             // 96*PA
    uint32_t* O1I = O1R + 96 * PA;

    int k   = blockIdx.y;
    int s0  = blockIdx.x * 64;
    int tid = threadIdx.x;
    int wrp = tid >> 5;
    int lane = tid & 31;
    int q = lane >> 2;
    int r = lane & 3;
    int ob = wrp * 16;

    float Or[8][4], Oi[8][4];

    {
        const float2* bb = (const float2*)b1_;
        float2 bv0 = bb[k * BS + ob + q];
        float2 bv1 = bb[k * BS + ob + q + 8];
        #pragma unroll
        for (int t = 0; t < 8; t++) {
            Or[t][0] = bv0.x; Or[t][1] = bv0.x; Or[t][2] = bv1.x; Or[t][3] = bv1.x;
            Oi[t][0] = bv0.y; Oi[t][1] = bv0.y; Oi[t][2] = bv1.y; Oi[t][3] = bv1.y;
        }
    }

    const float2* inb = in + (size_t)k * BS * S_;
    const float2* wb1 = (const float2*)w1_ + (size_t)k * BS * BS;
    const float2* wb2 = (const float2*)w2_ + (size_t)k * BS * BS;

    for (int ic = 0; ic < BS; ic += 32) {
        for (int t = tid; t < 32 * 96; t += 192) {
            int i = t / 96, o = t % 96;
            float2 wv = wb1[(size_t)(ic + i) * BS + o];
            WSR[i * PW + o] = f2tf(wv.x);
            WSI[i * PW + o] = f2tf(wv.y);
        }
        for (int t = tid; t < 32 * 64; t += 192) {
            int i = t >> 6, sl = t & 63;
            int s = s0 + sl;
            float2 v = (s < S_) ? inb[(size_t)(ic + i) * S_ + s]
                                : make_float2(0.f, 0.f);
            ASR[i * PA + sl] = f2tf(v.x);
            ASI[i * PA + sl] = f2tf(v.y);
        }
        __syncthreads();
        #pragma unroll
        for (int k0 = 0; k0 < 32; k0 += 8) {
            uint32_t awr0 = WSR[(k0 + r) * PW + ob + q];
            uint32_t awr1 = WSR[(k0 + r) * PW + ob + q + 8];
            uint32_t awr2 = WSR[(k0 + r + 4) * PW + ob + q];
            uint32_t awr3 = WSR[(k0 + r + 4) * PW + ob + q + 8];
            uint32_t awi0 = WSI[(k0 + r) * PW + ob + q];
            uint32_t awi1 = WSI[(k0 + r) * PW + ob + q + 8];
            uint32_t awi2 = WSI[(k0 + r + 4) * PW + ob + q];
            uint32_t awi3 = WSI[(k0 + r + 4) * PW + ob + q + 8];
            uint32_t nwi0 = awi0 ^ 0x80000000u, nwi1 = awi1 ^ 0x80000000u;
            uint32_t nwi2 = awi2 ^ 0x80000000u, nwi3 = awi3 ^ 0x80000000u;
            #pragma unroll
            for (int t = 0; t < 8; t++) {
                uint32_t br0 = ASR[(k0 + r) * PA + 8 * t + q];
                uint32_t br1 = ASR[(k0 + r + 4) * PA + 8 * t + q];
                uint32_t bi0 = ASI[(k0 + r) * PA + 8 * t + q];
                uint32_t bi1 = ASI[(k0 + r + 4) * PA + 8 * t + q];
                mma_tf32(Or[t], awr0, awr1, awr2, awr3, br0, br1);
                mma_tf32(Or[t], nwi0, nwi1, nwi2, nwi3, bi0, bi1);
                mma_tf32(Oi[t], awr0, awr1, awr2, awr3, bi0, bi1);
                mma_tf32(Oi[t], awi0, awi1, awi2, awi3, br0, br1);
            }
        }
        __syncthreads();
    }

    #pragma unroll
    for (int t = 0; t < 8; t++) {
        int sa = 8 * t + 2 * r;
        O1R[(ob + q    ) * PA + sa    ] = f2tf(fmaxf(Or[t][0], 0.f));
        O1R[(ob + q    ) * PA + sa + 1] = f2tf(fmaxf(Or[t][1], 0.f));
        O1R[(ob + q + 8) * PA + sa    ] = f2tf(fmaxf(Or[t][2], 0.f));
        O1R[(ob + q + 8) * PA + sa + 1] = f2tf(fmaxf(Or[t][3], 0.f));
        O1I[(ob + q    ) * PA + sa    ] = f2tf(fmaxf(Oi[t][0], 0.f));
        O1I[(ob + q    ) * PA + sa + 1] = f2tf(fmaxf(Oi[t][1], 0.f));
        O1I[(ob + q + 8) * PA + sa    ] = f2tf(fmaxf(Oi[t][2], 0.f));
        O1I[(ob + q + 8) * PA + sa + 1] = f2tf(fmaxf(Oi[t][3], 0.f));
    }
    {
        const float2* bb = (const float2*)b2_;
        float2 bv0 = bb[k * BS + ob + q];
        float2 bv1 = bb[k * BS + ob + q + 8];
        #pragma unroll
        for (int t = 0; t < 8; t++) {
            Or[t][0] = bv0.x; Or[t][1] = bv0.x; Or[t][2] = bv1.x; Or[t][3] = bv1.x;
            Oi[t][0] = bv0.y; Oi[t][1] = bv0.y; Oi[t][2] = bv1.y; Oi[t][3] = bv1.y;
        }
    }
    __syncthreads();

    for (int ic = 0; ic < BS; ic += 32) {
        for (int t = tid; t < 32 * 96; t += 192) {
            int i = t / 96, o = t % 96;
            float2 wv = wb2[(size_t)(ic + i) * BS + o];
            WSR[i * PW + o] = f2tf(wv.x);
            WSI[i * PW + o] = f2tf(wv.y);
        }
        __syncthreads();
        #pragma unroll
        for (int k0 = 0; k0 < 32; k0 += 8) {
            uint32_t awr0 = WSR[(k0 + r) * PW + ob + q];
            uint32_t awr1 = WSR[(k0 + r) * PW + ob + q + 8];
            uint32_t awr2 = WSR[(k0 + r + 4) * PW + ob + q];
            uint32_t awr3 = WSR[(k0 + r + 4) * PW + ob + q + 8];
            uint32_t awi0 = WSI[(k0 + r) * PW + ob + q];
            uint32_t awi1 = WSI[(k0 + r) * PW + ob + q + 8];
            uint32_t awi2 = WSI[(k0 + r + 4) * PW + ob + q];
            uint32_t awi3 = WSI[(k0 + r + 4) * PW + ob + q + 8];
            uint32_t nwi0 = awi0 ^ 0x80000000u, nwi1 = awi1 ^ 0x80000000u;
            uint32_t nwi2 = awi2 ^ 0x80000000u, nwi3 = awi3 ^ 0x80000000u;
            int kb = ic + k0;
            #pragma unroll
            for (int t = 0; t < 8; t++) {
                uint32_t br0 = O1R[(kb + r) * PA + 8 * t + q];
                uint32_t br1 = O1R[(kb + r + 4) * PA + 8 * t + q];
                uint32_t bi0 = O1I[(kb + r) * PA + 8 * t + q];
                uint32_t bi1 = O1I[(kb + r + 4) * PA + 8 * t + q];
                mma_tf32(Or[t], awr0, awr1, awr2, awr3, br0, br1);
                mma_tf32(Or[t], nwi0, nwi1, nwi2, nwi3, bi0, bi1);
                mma_tf32(Oi[t], awr0, awr1, awr2, awr3, bi0, bi1);
                mma_tf32(Oi[t], awi0, awi1, awi2, awi3, br0, br1);
            }
        }
        __syncthreads();
    }

    #pragma unroll
    for (int t = 0; t < 8; t++) {
        int sa = 8 * t + 2 * r;
        #pragma unroll
        for (int c = 0; c < 4; c++) {
            int o = ob + q + ((c >= 2) ? 8 : 0);
            int s = s0 + sa + (c & 1);
            if (s < S_) {
                float rr = Or[t][c], mm = Oi[t][c];
                rr = copysignf(fmaxf(fabsf(rr) - LAM, 0.f), rr);
                mm = copysignf(fmaxf(fabsf(mm) - LAM, 0.f), mm);
                out[(size_t)k * BS * S_ + (size_t)o * S_ + s] = make_float2(rr, mm);
            }
        }
    }
}

// ---------------------------------------------------------------------------
// Kernel 6: inverse c2r W DFT on TENSOR CORES (tf32).
// U[row][n] = sum_w Xr[w]*Uc[w][n] (w=0 col = 0.5), V = sum_w Xi*Vs.
// out[n] = 2*ORTHO*(U-V)+x, out[360-n] = 2*ORTHO*(U+V)+x (V=0 at n=0,180).
// M=192 n-outputs (6 warps x 2 mtiles), K=96 (chunks 32), N=64 rows/tile.
// ---------------------------------------------------------------------------
#define IPT 200
#define IPD 72
#define INV_SMEM_WORDS (2*32*IPT + 2*32*IPD)

__global__ __launch_bounds__(192)
void k_inv_w(const float* __restrict__ x, float* __restrict__ out) {
    extern __shared__ uint32_t smi[];
    uint32_t* UC = smi;                  // 32*IPT
    uint32_t* VS = UC + 32 * IPT;
    uint32_t* XR = VS + 32 * IPT;        // 32*IPD
    uint32_t* XI = XR + 32 * IPD;
    int r0  = blockIdx.x * 64;
    int tid = threadIdx.x;
    int wrp = tid >> 5, lane = tid & 31;
    int q = lane >> 2, r = lane & 3;

    float U[2][8][4], V[2][8][4];
    #pragma unroll
    for (int mt = 0; mt < 2; mt++)
        #pragma unroll
        for (int t = 0; t < 8; t++)
            #pragma unroll
            for (int c = 0; c < 4; c++) { U[mt][t][c] = 0.f; V[mt][t][c] = 0.f; }

    for (int w0 = 0; w0 < 96; w0 += 32) {
        for (int t = tid; t < 32 * 192; t += 192) {
            int i = t / 192, nn = t % 192;
            UC[i * IPT + nn] = g_UC[(w0 + i) * 192 + nn];
            VS[i * IPT + nn] = g_VS[(w0 + i) * 192 + nn];
        }
        for (int t = tid; t < 32 * 64; t += 192) {
            int i = t & 31, j = t >> 5;
            int w = w0 + i;
            float2 v = (w < WK) ? g_S2[(size_t)(r0 + j) * WK + w]
                                : make_float2(0.f, 0.f);
            XR[i * IPD + j] = f2tf(v.x);
            XI[i * IPD + j] = f2tf(v.y);
        }
        __syncthreads();
        #pragma unroll
        for (int mt = 0; mt < 2; mt++) {
            int mb = wrp * 32 + mt * 16;
            #pragma unroll
            for (int k0 = 0; k0 < 32; k0 += 8) {
                uint32_t au0 = UC[(k0 + r) * IPT + mb + q];
                uint32_t au1 = UC[(k0 + r) * IPT + mb + q + 8];
                uint32_t au2 = UC[(k0 + r + 4) * IPT + mb + q];
                uint32_t au3 = UC[(k0 + r + 4) * IPT + mb + q + 8];
                uint32_t av0 = VS[(k0 + r) * IPT + mb + q];
                uint32_t av1 = VS[(k0 + r) * IPT + mb + q + 8];
                uint32_t av2 = VS[(k0 + r + 4) * IPT + mb + q];
                uint32_t av3 = VS[(k0 + r + 4) * IPT + mb + q + 8];
                #pragma unroll
                for (int t = 0; t < 8; t++) {
                    uint32_t bR0 = XR[(k0 + r) * IPD + 8 * t + q];
                    uint32_t bR1 = XR[(k0 + r + 4) * IPD + 8 * t + q];
                    uint32_t bI0 = XI[(k0 + r) * IPD + 8 * t + q];
                    uint32_t bI1 = XI[(k0 + r + 4) * IPD + 8 * t + q];
                    mma_tf32(U[mt][t], au0, au1, au2, au3, bR0, bR1);
                    mma_tf32(V[mt][t], av0, av1, av2, av3, bI0, bI1);
                }
            }
        }
        __syncthreads();
    }

    const float k2 = 2.0f * ORTHO;
    #pragma unroll
    for (int mt = 0; mt < 2; mt++) {
        #pragma unroll
        for (int t = 0; t < 8; t++) {
            #pragma unroll
            for (int c = 0; c < 4; c++) {
                int n = wrp * 32 + mt * 16 + q + ((c >= 2) ? 8 : 0);
                int row = r0 + 8 * t + 2 * r + (c & 1);
                if (n <= 180) {
                    size_t rb = (size_t)row * W_;
                    float u = U[mt][t][c], v = V[mt][t][c];
                    out[rb + n] = fmaf(k2, u - v, x[rb + n]);
                    if (n >= 1 && n <= 179)
                        out[rb + W_ - n] = fmaf(k2, u + v, x[rb + W_ - n]);
                }
            }
        }
    }
}

// ---------------------------------------------------------------------------
extern "C" void kernel_launch(void* const* d_in, const int* in_sizes, int n_in,
                              void* d_out, int out_size) {
    const float* x  = (const float*)d_in[0];
    const float* w1 = (const float*)d_in[1];
    const float* b1 = (const float*)d_in[2];
    const float* w2 = (const float*)d_in[3];
    const float* b2 = (const float*)d_in[4];
    float* out = (float*)d_out;

    float2* S1; float2* S2;
    cudaGetSymbolAddress((void**)&S1, g_S1);
    cudaGetSymbolAddress((void**)&S2, g_S2);

    const int stiles   = (S_ + 63) / 64;           // 256
    const int mix_smem = MIX_SMEM_WORDS * 4;       // ~100 KB
    const int inv_smem = INV_SMEM_WORDS * 4;       // ~70 KB

    cudaFuncSetAttribute(k_mix_f,
                         cudaFuncAttributeMaxDynamicSharedMemorySize, mix_smem);
    cudaFuncSetAttribute(k_inv_w,
                         cudaFuncAttributeMaxDynamicSharedMemorySize, inv_smem);

    // 0. tf32 DFT tables + twiddles
    k_init_T<<<(192 * 96 + 255) / 256, 256>>>();
    // 1. forward W DFT on tensor cores (x -> S1), ortho-scaled
    k_fwd_w<<<ROWS / 64, 192>>>(x);
    // 2. forward H DFT (S1 -> S2)
    k_fft_h<-1><<<dim3(WK / WT, CH), 224>>>(S1, S2);
    // 3+4. fused tensor-core mix: relu(w1) then softshrink(w2)  (S2 -> S1)
    k_mix_f<<<dim3(stiles, NB), 192, mix_smem>>>(S2, S1, w1, b1, w2, b2);
    // 5. inverse H DFT (S1 -> S2)
    k_fft_h<+1><<<dim3(WK / WT, CH), 224>>>(S1, S2);
    // 6. inverse W c2r on tensor cores + residual (S2, x -> out)
    k_inv_w<<<ROWS / 64, 192, inv_smem>>>(x, out);
}

// round 17
// speedup vs baseline: 1.2540x; 1.2540x over previous
#include <cuda_runtime.h>
#include <math.h>
#include <stdint.h>

// Problem dims
#define CH   768
#define H_   180
#define W_   360
#define WK   91           // kept W modes (rfft bins 0..90; 91..180 provably zero)
#define NB   8
#define BS   96
#define S_   (H_ * WK)    // 16380 spectral points per channel
#define ROWS (CH * H_)    // 138240 spatial rows
#define ORTHO 0.003928371006591931f   // 1/sqrt(180*360)
#define LAM  0.01f

// Scratch buffers
__device__ float2 g_S1[(size_t)CH * S_];
__device__ float2 g_S2[(size_t)CH * S_];

// tf32-rounded DFT tables (stored as float bit patterns) + fp32 H twiddles
__device__ float2 g_Tfc[192 * 96];   // fwd: [n][w] = (cos, -sin); 0 outside n<=180,w<=90
__device__ float2 g_Tic[96 * 192];   // inv: [w][n] = (cos, sin); w=0 -> (0.5, 0)
__device__ float2 g_twHf[H_];        // e^{-2pi i n/180}
__device__ float2 g_twHb[H_];        // e^{+2pi i n/180}

__device__ __forceinline__ float2 cmul(float2 a, float2 b) {
    return make_float2(fmaf(a.x, b.x, -a.y * b.y),
                       fmaf(a.x, b.y,  a.y * b.x));
}

__device__ __forceinline__ float f2tf_f(float f) {
    uint32_t u;
    asm("cvt.rna.tf32.f32 %0, %1;" : "=r"(u) : "f"(f));
    return __uint_as_float(u);
}

// mma.m16n8k8 tf32: raw fp32 bits are truncated to tf32 by HW.
__device__ __forceinline__ void mma_tf32(float* d,
    float a0, float a1, float a2, float a3, float b0, float b1) {
    asm volatile(
        "mma.sync.aligned.m16n8k8.row.col.f32.tf32.tf32.f32 "
        "{%0,%1,%2,%3}, {%4,%5,%6,%7}, {%8,%9}, {%0,%1,%2,%3};"
        : "+f"(d[0]), "+f"(d[1]), "+f"(d[2]), "+f"(d[3])
        : "r"(__float_as_uint(a0)), "r"(__float_as_uint(a1)),
          "r"(__float_as_uint(a2)), "r"(__float_as_uint(a3)),
          "r"(__float_as_uint(b0)), "r"(__float_as_uint(b1)));
}

// ---------------------------------------------------------------------------
// Init: tf32-rounded DFT tables + H twiddles.
// ---------------------------------------------------------------------------
__global__ void k_init_T() {
    int i = blockIdx.x * 256 + threadIdx.x;
    if (i < 192 * 96) {                      // fwd [n][w]
        int n = i / 96, w = i % 96;
        float cv = 0.f, sv = 0.f;
        if (n <= 180 && w <= 90) {
            float s, c;
            sincospif((float)((n * w) % 360) / 180.0f, &s, &c);
            cv = f2tf_f(c); sv = f2tf_f(-s);
        }
        g_Tfc[i] = make_float2(cv, sv);
    }
    if (i < 96 * 192) {                      // inv [w][n]
        int w = i / 192, n = i % 192;
        float uc = 0.f, vs = 0.f;
        if (n <= 180 && w <= 90) {
            if (w == 0) uc = 0.5f;
            else {
                float s, c;
                sincospif((float)((n * w) % 360) / 180.0f, &s, &c);
                uc = f2tf_f(c); vs = f2tf_f(s);
            }
        }
        g_Tic[i] = make_float2(uc, vs);
    }
    if (i < H_) {
        float s, c;
        sincospif((float)i / 90.0f, &s, &c);
        g_twHf[i] = make_float2(c, -s);
        g_twHb[i] = make_float2(c,  s);
    }
}

// ---------------------------------------------------------------------------
// Kernel 1: forward W r2c DFT on tensor cores. Interleaved (cos,-sin)/(p,m)
// smem; fragments via LDS.64. M=96 bins, K=192, N=64 rows/CTA. Static smem.
// ---------------------------------------------------------------------------
#define FTS 100   // float2 stride, 200 words == 8 mod 32
#define FDS 68    // float2 stride, 136 words == 8 mod 32
__global__ __launch_bounds__(192)
void k_fwd_w(const float* __restrict__ x) {
    __shared__ float2 TT[32 * FTS];   // (cos, -sin)
    __shared__ float2 PM[32 * FDS];   // (p, m)
    int r0  = blockIdx.x * 64;
    int tid = threadIdx.x;
    int wrp = tid >> 5, lane = tid & 31;
    int q = lane >> 2, r = lane & 3;
    int wb = wrp * 16;

    float Or[8][4], Oi[8][4];
    #pragma unroll
    for (int t = 0; t < 8; t++)
        #pragma unroll
        for (int c = 0; c < 4; c++) { Or[t][c] = 0.f; Oi[t][c] = 0.f; }

    for (int nc = 0; nc < 192; nc += 32) {
        #pragma unroll
        for (int t = tid; t < 32 * 48; t += 192) {     // table, float4 = 2 cmplx
            int i = t / 48, wp = t % 48;
            const float4* src =
                reinterpret_cast<const float4*>(g_Tfc + (nc + i) * 96) + wp;
            *reinterpret_cast<float4*>(&TT[i * FTS + 2 * wp]) = *src;
        }
        for (int t = tid; t < 32 * 64; t += 192) {     // fold staging
            int i = t & 31, j = t >> 5;
            int n = nc + i;
            const float* xr = x + (size_t)(r0 + j) * W_;
            float a = (n <= 180) ? xr[n] : 0.f;
            float b = (n >= 1 && n <= 179) ? xr[W_ - n] : 0.f;
            PM[i * FDS + j] = make_float2(a + b, a - b);
        }
        __syncthreads();
        #pragma unroll
        for (int k0 = 0; k0 < 32; k0 += 8) {
            int kr = k0 + r, kr4 = k0 + r + 4;
            float2 A0 = TT[kr  * FTS + wb + q];
            float2 A1 = TT[kr  * FTS + wb + q + 8];
            float2 A2 = TT[kr4 * FTS + wb + q];
            float2 A3 = TT[kr4 * FTS + wb + q + 8];
            #pragma unroll
            for (int t = 0; t < 8; t++) {
                float2 B0 = PM[kr  * FDS + 8 * t + q];
                float2 B1 = PM[kr4 * FDS + 8 * t + q];
                mma_tf32(Or[t], A0.x, A1.x, A2.x, A3.x, B0.x, B1.x);
                mma_tf32(Oi[t], A0.y, A1.y, A2.y, A3.y, B0.y, B1.y);
            }
        }
        __syncthreads();
    }
    #pragma unroll
    for (int t = 0; t < 8; t++) {
        #pragma unroll
        for (int c = 0; c < 4; c++) {
            int bin = wb + q + ((c >= 2) ? 8 : 0);
            int row = r0 + 8 * t + 2 * r + (c & 1);
            if (bin < WK)
                g_S1[(size_t)row * WK + bin] =
                    make_float2(Or[t][c] * ORTHO, Oi[t][c] * ORTHO);
        }
    }
}

// ---------------------------------------------------------------------------
// Kernels 2/5: 180-pt complex DFT along H (unchanged, proven).
// ---------------------------------------------------------------------------
#define WT 13
template <int SGN>
__global__ __launch_bounds__(224)
void k_fft_h(const float2* __restrict__ in, float2* __restrict__ out) {
    __shared__ float2 tile[H_ * WT];
    __shared__ float2 tw[H_];
    int c  = blockIdx.y;
    int w0 = blockIdx.x * WT;
    const float2* base = in + (size_t)c * S_;
    for (int i = threadIdx.x; i < H_ * WT; i += 224) {
        int h = i / WT, wl = i % WT;
        tile[i] = base[(size_t)h * WK + w0 + wl];
    }
    const float2* gt = (SGN < 0) ? g_twHf : g_twHb;
    for (int n = threadIdx.x; n < H_; n += 224) tw[n] = gt[n];
    __syncthreads();

    int tid = threadIdx.x;
    if (tid < 195) {
        int k0 = tid / WT, wl = tid % WT;
        float2 w60  = tw[60];
        float2 w120 = tw[120];
        int s4 = 4 * k0;

        float2 A[3][4];
        #pragma unroll
        for (int t = 0; t < 3; t++)
            #pragma unroll
            for (int j = 0; j < 4; j++) A[t][j] = make_float2(0.f, 0.f);

        int idx = 0;
        #pragma unroll 3
        for (int q = 0; q < 15; q++) {
            #pragma unroll
            for (int u = 0; u < 3; u++) {
                int r = 3 * q + u;
                float2 e0 = tw[idx];
                float2 e1, e2;
                if (u == 0)      { e1 = e0; e2 = e0; }
                else if (u == 1) { e1 = cmul(e0, w60);  e2 = cmul(e0, w120); }
                else             { e1 = cmul(e0, w120); e2 = cmul(e0, w60);  }
                float2 z0 = tile[(4 * r + 0) * WT + wl];
                float2 z1 = tile[(4 * r + 1) * WT + wl];
                float2 z2 = tile[(4 * r + 2) * WT + wl];
                float2 z3 = tile[(4 * r + 3) * WT + wl];
                #pragma unroll
                for (int t = 0; t < 3; t++) {
                    float2 e = (t == 0) ? e0 : (t == 1) ? e1 : e2;
                    A[t][0].x = fmaf(z0.x, e.x, fmaf(-z0.y, e.y, A[t][0].x));
                    A[t][0].y = fmaf(z0.x, e.y, fmaf( z0.y, e.x, A[t][0].y));
                    A[t][1].x = fmaf(z1.x, e.x, fmaf(-z1.y, e.y, A[t][1].x));
                    A[t][1].y = fmaf(z1.x, e.y, fmaf( z1.y, e.x, A[t][1].y));
                    A[t][2].x = fmaf(z2.x, e.x, fmaf(-z2.y, e.y, A[t][2].x));
                    A[t][2].y = fmaf(z2.x, e.y, fmaf( z2.y, e.x, A[t][2].y));
                    A[t][3].x = fmaf(z3.x, e.x, fmaf(-z3.y, e.y, A[t][3].x));
                    A[t][3].y = fmaf(z3.x, e.y, fmaf( z3.y, e.x, A[t][3].y));
                }
                idx += s4; if (idx >= H_) idx -= H_;
            }
        }

        float2* ob = out + (size_t)c * S_;
        #pragma unroll
        for (int t = 0; t < 3; t++) {
            int kt = k0 + 15 * t;
            float2 PP = A[t][0], QP = A[t][1], PQ = A[t][2], QQ = A[t][3];
            float2 w1t = tw[kt];
            float2 w2t = tw[2 * kt];
            float2 t2  = cmul(w2t, PQ);
            float2 t2q = cmul(w2t, QQ);
            float2 Pp = make_float2(PP.x + t2.x,  PP.y + t2.y);
            float2 Pm = make_float2(PP.x - t2.x,  PP.y - t2.y);
            float2 Qp = make_float2(QP.x + t2q.x, QP.y + t2q.y);
            float2 Qm = make_float2(QP.x - t2q.x, QP.y - t2q.y);
            float2 up = cmul(w1t, Qp);
            float2 um = cmul(w1t, Qm);
            float2 iu = make_float2((float)(-SGN) * um.y, (float)SGN * um.x);
            size_t o0 = (size_t)kt * WK + w0 + wl;
            ob[o0           ] = make_float2(Pp.x + up.x, Pp.y + up.y);
            ob[o0 +  45 * WK] = make_float2(Pm.x + iu.x, Pm.y + iu.y);
            ob[o0 +  90 * WK] = make_float2(Pp.x - up.x, Pp.y - up.y);
            ob[o0 + 135 * WK] = make_float2(Pm.x - iu.x, Pm.y - iu.y);
        }
    }
}

// ---------------------------------------------------------------------------
// Kernels 3+4 fused on tensor cores, interleaved complex smem.
// o2 = softshrink(w2 @ relu(w1 @ in + b1) + b2); 4 real mmas per cmplx tile.
// ---------------------------------------------------------------------------
#define MWS 100   // weight float2 stride (200 words == 8 mod 32)
#define MAS 68    // data/o1 float2 stride (136 words == 8 mod 32)
#define MIX_SMEM_BYTES ((32 * MWS + 32 * MAS + 96 * MAS) * (int)sizeof(float2))

__global__ __launch_bounds__(192)
void k_mix_f(const float2* __restrict__ in, float2* __restrict__ out,
             const float* __restrict__ w1_, const float* __restrict__ b1_,
             const float* __restrict__ w2_, const float* __restrict__ b2_) {
    extern __shared__ float2 smc[];
    float2* WS = smc;                     // 32 x MWS  (weights, (r,i))
    float2* AS = WS + 32 * MWS;           // 32 x MAS  (data)
    float2* O1 = AS + 32 * MAS;           // 96 x MAS  (intermediate)

    int k   = blockIdx.y;
    int s0  = blockIdx.x * 64;
    int tid = threadIdx.x;
    int wrp = tid >> 5, lane = tid & 31;
    int q = lane >> 2, r = lane & 3;
    int ob = wrp * 16;

    float Or[8][4], Oi[8][4];
    {
        const float2* bb = (const float2*)b1_;
        float2 bv0 = bb[k * BS + ob + q];
        float2 bv1 = bb[k * BS + ob + q + 8];
        #pragma unroll
        for (int t = 0; t < 8; t++) {
            Or[t][0] = bv0.x; Or[t][1] = bv0.x; Or[t][2] = bv1.x; Or[t][3] = bv1.x;
            Oi[t][0] = bv0.y; Oi[t][1] = bv0.y; Oi[t][2] = bv1.y; Oi[t][3] = bv1.y;
        }
    }

    const float2* inb = in + (size_t)k * BS * S_;
    const float2* wb1 = (const float2*)w1_ + (size_t)k * BS * BS;
    const float2* wb2 = (const float2*)w2_ + (size_t)k * BS * BS;

    // ---- GEMM 1 ----
    for (int ic = 0; ic < BS; ic += 32) {
        #pragma unroll
        for (int t = tid; t < 32 * 48; t += 192) {     // weights, float4
            int i = t / 48, wp = t % 48;
            const float4* src =
                reinterpret_cast<const float4*>(wb1 + (size_t)(ic + i) * BS) + wp;
            *reinterpret_cast<float4*>(&WS[i * MWS + 2 * wp]) = *src;
        }
        for (int t = tid; t < 32 * 32; t += 192) {     // data, float4 = 2 spatial
            int i = t >> 5, sp = t & 31;
            int s = s0 + 2 * sp;
            float4 v;
            if (s + 1 < S_) {
                v = *(reinterpret_cast<const float4*>(inb + (size_t)(ic + i) * S_ + s));
            } else if (s < S_) {
                float2 e = inb[(size_t)(ic + i) * S_ + s];
                v = make_float4(e.x, e.y, 0.f, 0.f);
            } else {
                v = make_float4(0.f, 0.f, 0.f, 0.f);
            }
            *reinterpret_cast<float4*>(&AS[i * MAS + 2 * sp]) = v;
        }
        __syncthreads();
        #pragma unroll
        for (int k0 = 0; k0 < 32; k0 += 8) {
            int kr = k0 + r, kr4 = k0 + r + 4;
            float2 W0 = WS[kr  * MWS + ob + q];
            float2 W1 = WS[kr  * MWS + ob + q + 8];
            float2 W2 = WS[kr4 * MWS + ob + q];
            float2 W3 = WS[kr4 * MWS + ob + q + 8];
            #pragma unroll
            for (int t = 0; t < 8; t++) {
                float2 B0 = AS[kr  * MAS + 8 * t + q];
                float2 B1 = AS[kr4 * MAS + 8 * t + q];
                mma_tf32(Or[t],  W0.x,  W1.x,  W2.x,  W3.x, B0.x, B1.x);
                mma_tf32(Or[t], -W0.y, -W1.y, -W2.y, -W3.y, B0.y, B1.y);
                mma_tf32(Oi[t],  W0.x,  W1.x,  W2.x,  W3.x, B0.y, B1.y);
                mma_tf32(Oi[t],  W0.y,  W1.y,  W2.y,  W3.y, B0.x, B1.x);
            }
        }
        __syncthreads();
    }

    // relu -> O1 [o][s] interleaved
    #pragma unroll
    for (int t = 0; t < 8; t++) {
        int sa = 8 * t + 2 * r;
        O1[(ob + q    ) * MAS + sa    ] =
            make_float2(fmaxf(Or[t][0], 0.f), fmaxf(Oi[t][0], 0.f));
        O1[(ob + q    ) * MAS + sa + 1] =
            make_float2(fmaxf(Or[t][1], 0.f), fmaxf(Oi[t][1], 0.f));
        O1[(ob + q + 8) * MAS + sa    ] =
            make_float2(fmaxf(Or[t][2], 0.f), fmaxf(Oi[t][2], 0.f));
        O1[(ob + q + 8) * MAS + sa + 1] =
            make_float2(fmaxf(Or[t][3], 0.f), fmaxf(Oi[t][3], 0.f));
    }
    {
        const float2* bb = (const float2*)b2_;
        float2 bv0 = bb[k * BS + ob + q];
        float2 bv1 = bb[k * BS + ob + q + 8];
        #pragma unroll
        for (int t = 0; t < 8; t++) {
            Or[t][0] = bv0.x; Or[t][1] = bv0.x; Or[t][2] = bv1.x; Or[t][3] = bv1.x;
            Oi[t][0] = bv0.y; Oi[t][1] = bv0.y; Oi[t][2] = bv1.y; Oi[t][3] = bv1.y;
        }
    }
    __syncthreads();

    // ---- GEMM 2 (B operand = O1) ----
    for (int ic = 0; ic < BS; ic += 32) {
        #pragma unroll
        for (int t = tid; t < 32 * 48; t += 192) {
            int i = t / 48, wp = t % 48;
            const float4* src =
                reinterpret_cast<const float4*>(wb2 + (size_t)(ic + i) * BS) + wp;
            *reinterpret_cast<float4*>(&WS[i * MWS + 2 * wp]) = *src;
        }
        __syncthreads();
        #pragma unroll
        for (int k0 = 0; k0 < 32; k0 += 8) {
            int kr = k0 + r, kr4 = k0 + r + 4;
            float2 W0 = WS[kr  * MWS + ob + q];
            float2 W1 = WS[kr  * MWS + ob + q + 8];
            float2 W2 = WS[kr4 * MWS + ob + q];
            float2 W3 = WS[kr4 * MWS + ob + q + 8];
            int kb = ic + k0;
            #pragma unroll
            for (int t = 0; t < 8; t++) {
                float2 B0 = O1[(kb + r    ) * MAS + 8 * t + q];
                float2 B1 = O1[(kb + r + 4) * MAS + 8 * t + q];
                mma_tf32(Or[t],  W0.x,  W1.x,  W2.x,  W3.x, B0.x, B1.x);
                mma_tf32(Or[t], -W0.y, -W1.y, -W2.y, -W3.y, B0.y, B1.y);
                mma_tf32(Oi[t],  W0.x,  W1.x,  W2.x,  W3.x, B0.y, B1.y);
                mma_tf32(Oi[t],  W0.y,  W1.y,  W2.y,  W3.y, B0.x, B1.x);
            }
        }
        __syncthreads();
    }

    // softshrink epilogue
    #pragma unroll
    for (int t = 0; t < 8; t++) {
        int sa = 8 * t + 2 * r;
        #pragma unroll
        for (int c = 0; c < 4; c++) {
            int o = ob + q + ((c >= 2) ? 8 : 0);
            int s = s0 + sa + (c & 1);
            if (s < S_) {
                float rr = Or[t][c], mm = Oi[t][c];
                rr = copysignf(fmaxf(fabsf(rr) - LAM, 0.f), rr);
                mm = copysignf(fmaxf(fabsf(mm) - LAM, 0.f), mm);
                out[(size_t)k * BS * S_ + (size_t)o * S_ + s] = make_float2(rr, mm);
            }
        }
    }
}

// ---------------------------------------------------------------------------
// Kernel 6: inverse c2r W DFT on tensor cores, interleaved (Uc,Vs)/(Xr,Xi).
// out[n] = 2*ORTHO*(U-V)+x, out[360-n] = 2*ORTHO*(U+V)+x.
// M=192 n-outputs (6 warps x 2 mtiles), K=96, N=64 rows/CTA.
// ---------------------------------------------------------------------------
#define ITS 196   // table float2 stride (392 words == 8 mod 32)
#define IDS 68
#define INV_SMEM_BYTES ((32 * ITS + 32 * IDS) * (int)sizeof(float2))

__global__ __launch_bounds__(192)
void k_inv_w(const float* __restrict__ x, float* __restrict__ out) {
    extern __shared__ float2 smi[];
    float2* UV = smi;                    // 32 x ITS (Uc, Vs)
    float2* XX = UV + 32 * ITS;          // 32 x IDS (Xr, Xi)
    int r0  = blockIdx.x * 64;
    int tid = threadIdx.x;
    int wrp = tid >> 5, lane = tid & 31;
    int q = lane >> 2, r = lane & 3;

    float U[2][8][4], V[2][8][4];
    #pragma unroll
    for (int mt = 0; mt < 2; mt++)
        #pragma unroll
        for (int t = 0; t < 8; t++)
            #pragma unroll
            for (int c = 0; c < 4; c++) { U[mt][t][c] = 0.f; V[mt][t][c] = 0.f; }

    for (int w0 = 0; w0 < 96; w0 += 32) {
        #pragma unroll
        for (int t = tid; t < 32 * 96; t += 192) {     // table, float4
            int i = t / 96, cp = t % 96;
            const float4* src =
                reinterpret_cast<const float4*>(g_Tic + (w0 + i) * 192) + cp;
            *reinterpret_cast<float4*>(&UV[i * ITS + 2 * cp]) = *src;
        }
        for (int t = tid; t < 32 * 64; t += 192) {     // spectra
            int i = t & 31, j = t >> 5;
            int w = w0 + i;
            float2 v = (w < WK) ? g_S2[(size_t)(r0 + j) * WK + w]
                                : make_float2(0.f, 0.f);
            XX[i * IDS + j] = v;
        }
        __syncthreads();
        #pragma unroll
        for (int mt = 0; mt < 2; mt++) {
            int mb = wrp * 32 + mt * 16;
            #pragma unroll
            for (int k0 = 0; k0 < 32; k0 += 8) {
                int kr = k0 + r, kr4 = k0 + r + 4;
                float2 A0 = UV[kr  * ITS + mb + q];
                float2 A1 = UV[kr  * ITS + mb + q + 8];
                float2 A2 = UV[kr4 * ITS + mb + q];
                float2 A3 = UV[kr4 * ITS + mb + q + 8];
                #pragma unroll
                for (int t = 0; t < 8; t++) {
                    float2 B0 = XX[kr  * IDS + 8 * t + q];
                    float2 B1 = XX[kr4 * IDS + 8 * t + q];
                    mma_tf32(U[mt][t], A0.x, A1.x, A2.x, A3.x, B0.x, B1.x);
                    mma_tf32(V[mt][t], A0.y, A1.y, A2.y, A3.y, B0.y, B1.y);
                }
            }
        }
        __syncthreads();
    }

    const float k2 = 2.0f * ORTHO;
    #pragma unroll
    for (int mt = 0; mt < 2; mt++) {
        #pragma unroll
        for (int t = 0; t < 8; t++) {
            #pragma unroll
            for (int c = 0; c < 4; c++) {
                int n = wrp * 32 + mt * 16 + q + ((c >= 2) ? 8 : 0);
                int row = r0 + 8 * t + 2 * r + (c & 1);
                if (n <= 180) {
                    size_t rb = (size_t)row * W_;
                    float u = U[mt][t][c], v = V[mt][t][c];
                    out[rb + n] = fmaf(k2, u - v, x[rb + n]);
                    if (n >= 1 && n <= 179)
                        out[rb + W_ - n] = fmaf(k2, u + v, x[rb + W_ - n]);
                }
            }
        }
    }
}

// ---------------------------------------------------------------------------
extern "C" void kernel_launch(void* const* d_in, const int* in_sizes, int n_in,
                              void* d_out, int out_size) {
    const float* x  = (const float*)d_in[0];
    const float* w1 = (const float*)d_in[1];
    const float* b1 = (const float*)d_in[2];
    const float* w2 = (const float*)d_in[3];
    const float* b2 = (const float*)d_in[4];
    float* out = (float*)d_out;

    float2* S1; float2* S2;
    cudaGetSymbolAddress((void**)&S1, g_S1);
    cudaGetSymbolAddress((void**)&S2, g_S2);

    const int stiles = (S_ + 63) / 64;             // 256

    cudaFuncSetAttribute(k_mix_f,
                         cudaFuncAttributeMaxDynamicSharedMemorySize, MIX_SMEM_BYTES);
    cudaFuncSetAttribute(k_inv_w,
                         cudaFuncAttributeMaxDynamicSharedMemorySize, INV_SMEM_BYTES);

    // 0. tf32 DFT tables + twiddles
    k_init_T<<<(96 * 192 + 255) / 256, 256>>>();
    // 1. forward W DFT on tensor cores (x -> S1), ortho-scaled
    k_fwd_w<<<ROWS / 64, 192>>>(x);
    // 2. forward H DFT (S1 -> S2)
    k_fft_h<-1><<<dim3(WK / WT, CH), 224>>>(S1, S2);
    // 3+4. fused tensor-core mix (S2 -> S1)
    k_mix_f<<<dim3(stiles, NB), 192, MIX_SMEM_BYTES>>>(S2, S1, w1, b1, w2, b2);
    // 5. inverse H DFT (S1 -> S2)
    k_fft_h<+1><<<dim3(WK / WT, CH), 224>>>(S1, S2);
    // 6. inverse W c2r on tensor cores + residual (S2, x -> out)
    k_inv_w<<<ROWS / 64, 192, INV_SMEM_BYTES>>>(x, out);
}